// round 17
// baseline (speedup 1.0000x reference)
#include <cuda_runtime.h>
#include <math.h>
#include <float.h>

#define BB 8
#define CC 256
#define HH 224
#define WW 224
#define CELLS 16
#define HW (HH*WW)
#define NUM_LEVELS 3
#define BLK_PER_B 256           // one channel per block

// scratch (no allocations allowed)
__device__ float    g_coarse[BB*CC*CELLS];  // [b][c][cell]
__device__ float    g_mask[BB*CELLS];
__device__ unsigned g_counter[BB];          // monotonic across replays
__device__ unsigned g_flag[BB];             // monotonic epoch per batch

// ---------------------------------------------------------------------------
// Mega-kernel: 2048 blocks = 8 batches x 256 channels, 224 threads.
// Each block: pool own channel (read x once, DRAM) -> per-batch barrier via
// atomic counter (last block computes mask/keep/coords) -> spin on epoch ->
// sparse multiply re-reading own channel (L2-hot) and streaming the output.
// Blocks from adjacent batches pipeline: reads and writes mix continuously.
// Residency (4 blocks/SM * 148 = 592 >= 2*256) guarantees the oldest
// incomplete batch is always fully resident -> no deadlock.
// ---------------------------------------------------------------------------
__global__ void __launch_bounds__(224, 4)
k_fused(const float* __restrict__ x, float4* __restrict__ o4,
        const float* __restrict__ logit_th,
        float* __restrict__ out_keep, float* __restrict__ out_coords)
{
    const float4* x4 = (const float4*)x;
    int bid = blockIdx.x;
    int b = bid >> 8;               // batch
    int c = bid & 255;              // channel
    int t = threadIdx.x;            // 0..223
    int col4 = t % 56, row0 = t / 56;
    size_t cb4 = (size_t)(b*CC + c) * (HH*56);   // channel base in float4

    __shared__ unsigned s_epoch;
    __shared__ float    scell[4*224];            // [gy][t]
    __shared__ float    sw[CELLS][7];
    __shared__ float    simp[CELLS];
    __shared__ float    s_m[CELLS];
    __shared__ int      s_last;

    if (t == 0) s_epoch = *((volatile unsigned*)&g_flag[b]);

    // ---- Phase 1: pool own channel. row r = row0 + 4j, gy = j/14 ----------
    float cm0 = -FLT_MAX, cm1 = -FLT_MAX, cm2 = -FLT_MAX, cm3 = -FLT_MAX;
    #pragma unroll
    for (int jo = 0; jo < 56; jo += 8) {
        float4 v[8];
        #pragma unroll
        for (int k = 0; k < 8; k++)
            v[k] = __ldg(&x4[cb4 + (size_t)(row0 + 4*(jo + k))*56 + col4]);
        #pragma unroll
        for (int k = 0; k < 8; k++) {
            float m = fmaxf(fmaxf(v[k].x, v[k].y), fmaxf(v[k].z, v[k].w));
            int gy = (jo + k) / 14;              // compile-time constant
            if (gy == 0)      cm0 = fmaxf(cm0, m);
            else if (gy == 1) cm1 = fmaxf(cm1, m);
            else if (gy == 2) cm2 = fmaxf(cm2, m);
            else              cm3 = fmaxf(cm3, m);
        }
    }
    scell[0*224 + t] = cm0; scell[1*224 + t] = cm1;
    scell[2*224 + t] = cm2; scell[3*224 + t] = cm3;
    __syncthreads();
    if (t < CELLS) {                             // t: gy = t>>2, gx = t&3
        int gy = t >> 2, gx = t & 3;
        float m = -FLT_MAX;
        #pragma unroll
        for (int r0 = 0; r0 < 4; r0++)
            #pragma unroll
            for (int q = 0; q < 14; q++)
                m = fmaxf(m, scell[gy*224 + r0*56 + gx*14 + q]);
        g_coarse[((size_t)(b*CC + c))*CELLS + t] = m;
    }
    __syncthreads();

    __threadfence();
    if (t == 0) {
        unsigned old = atomicAdd(&g_counter[b], 1u);
        s_last = ((old & (BLK_PER_B - 1u)) == BLK_PER_B - 1u) ? 1 : 0;
    }
    __syncthreads();

    // ---- Phase 2: last block of this batch -> mask/keep/coords ------------
    if (s_last) {
        __threadfence();
        float acc[CELLS];
        #pragma unroll
        for (int n = 0; n < CELLS; n++) acc[n] = 0.f;
        for (int ch = t; ch < CC; ch += 224) {
            const float* row = g_coarse + ((size_t)b*CC + ch)*CELLS;
            #pragma unroll
            for (int n = 0; n < CELLS; n++) { float v = row[n]; acc[n] = fmaf(v, v, acc[n]); }
        }
        int lane = t & 31, wid = t >> 5;         // 7 full warps
        #pragma unroll
        for (int n = 0; n < CELLS; n++) {
            float r = acc[n];
            #pragma unroll
            for (int o = 16; o; o >>= 1) r += __shfl_down_sync(0xffffffffu, r, o);
            if (lane == 0) sw[n][wid] = r;
        }
        __syncthreads();
        if (t < CELLS) {
            float ssum = 0.f;
            #pragma unroll
            for (int w = 0; w < 7; w++) ssum += sw[t][w];
            simp[t] = sqrtf(ssum);
        }
        __syncthreads();
        if (t < CELLS) {
            float mn = simp[0], mx = simp[0];
            #pragma unroll
            for (int n = 1; n < CELLS; n++) { mn = fminf(mn, simp[n]); mx = fmaxf(mx, simp[n]); }
            float imp01 = (simp[t] - mn) / (mx - mn + 1e-8f);
            float th   = 1.f / (1.f + expf(-logit_th[NUM_LEVELS - 1]));
            float hard = (imp01 >= th) ? 1.f : 0.f;
            float soft = 1.f / (1.f + expf(-(imp01 - th) * 10.f));
            float mask = fmaxf((hard - soft) + soft, 0.f);
            g_mask[b*CELLS + t] = mask;
            float keep = (mask > 0.5f) ? 1.f : 0.f;
            out_keep[b*CELLS + t] = keep;
            int r = t >> 2, cx = t & 3;
            ((float4*)out_coords)[b*CELLS + t] =
                make_float4((cx + 0.5f)*0.25f*keep, (r + 0.5f)*0.25f*keep,
                            0.25f*keep, 0.25f*keep);
        }
        __threadfence();
        __syncthreads();
        if (t == 0) atomicAdd(&g_flag[b], 1u);
    }

    // ---- Phase 3: spin until this batch's mask is ready -------------------
    if (t == 0) {
        while (*((volatile unsigned*)&g_flag[b]) == s_epoch) __nanosleep(32);
        __threadfence();
    }
    __syncthreads();
    if (t < CELLS) s_m[t] = __ldcg(&g_mask[b*CELLS + t]);
    __syncthreads();

    // ---- Phase 4: sparse multiply over own channel (L2-hot) ---------------
    float wx[4]; int jxA[4];
    #pragma unroll
    for (int i = 0; i < 4; i++) {
        float tx = fminf(fmaxf((col4*4 + i + 0.5f)*(1.f/56.f) - 0.5f, 0.f), 3.f);
        int jx = min((int)tx, 2);
        jxA[i] = jx; wx[i] = tx - (float)jx;
    }
    #pragma unroll
    for (int jo = 0; jo < 56; jo += 8) {
        float4 v[8];
        #pragma unroll
        for (int k = 0; k < 8; k++)
            v[k] = __ldcs(&x4[cb4 + (size_t)(row0 + 4*(jo + k))*56 + col4]);
        #pragma unroll
        for (int k = 0; k < 8; k++) {
            int y = row0 + 4*(jo + k);
            float ty = fminf(fmaxf((y + 0.5f)*(1.f/56.f) - 0.5f, 0.f), 3.f);
            int jy = min((int)ty, 2);
            float fy = ty - (float)jy;
            float r0 = s_m[jy*4+0] + (s_m[jy*4+4] - s_m[jy*4+0])*fy;
            float r1 = s_m[jy*4+1] + (s_m[jy*4+5] - s_m[jy*4+1])*fy;
            float r2 = s_m[jy*4+2] + (s_m[jy*4+6] - s_m[jy*4+2])*fy;
            float r3 = s_m[jy*4+3] + (s_m[jy*4+7] - s_m[jy*4+3])*fy;
            float mk[4];
            #pragma unroll
            for (int i = 0; i < 4; i++) {
                float a  = (jxA[i] == 0) ? r0 : (jxA[i] == 1) ? r1 : r2;
                float c2 = (jxA[i] == 0) ? r1 : (jxA[i] == 1) ? r2 : r3;
                mk[i] = a + (c2 - a)*wx[i];
            }
            size_t idx = cb4 + (size_t)y*56 + col4;
            __stcs(&o4[idx], make_float4(v[k].x*mk[0], v[k].y*mk[1],
                                         v[k].z*mk[2], v[k].w*mk[3]));
        }
    }
}

// ---------------------------------------------------------------------------
// LayerNorm + Linear over coarse cells, gated by keep.
// ---------------------------------------------------------------------------
__global__ void k_proj(const float* __restrict__ gamma, const float* __restrict__ beta,
                       const float* __restrict__ wproj, const float* __restrict__ bproj,
                       float* __restrict__ out_feats) {
    int bn = blockIdx.x;             // b*16 + n
    int b = bn >> 4, n = bn & 15;
    int t = threadIdx.x;
    __shared__ float sf[256];
    __shared__ float sred[8];

    float f = g_coarse[((size_t)b*CC + t)*CELLS + n];
    int lane = t & 31, wid = t >> 5;

    float s = f;
    #pragma unroll
    for (int o = 16; o; o >>= 1) s += __shfl_down_sync(0xffffffffu, s, o);
    if (lane == 0) sred[wid] = s;
    __syncthreads();
    float mean = 0.f;
    #pragma unroll
    for (int w = 0; w < 8; w++) mean += sred[w];
    mean *= (1.f/256.f);
    __syncthreads();

    float d = f - mean;
    s = d*d;
    #pragma unroll
    for (int o = 16; o; o >>= 1) s += __shfl_down_sync(0xffffffffu, s, o);
    if (lane == 0) sred[wid] = s;
    __syncthreads();
    float var = 0.f;
    #pragma unroll
    for (int w = 0; w < 8; w++) var += sred[w];
    var *= (1.f/256.f);

    sf[t] = d * rsqrtf(var + 1e-5f) * gamma[t] + beta[t];
    __syncthreads();

    float acc = bproj[t];
    #pragma unroll 8
    for (int c = 0; c < 256; c++) acc = fmaf(sf[c], wproj[c*256 + t], acc);
    float keep = (g_mask[bn] > 0.5f) ? 1.f : 0.f;
    out_feats[(size_t)bn*256 + t] = acc * keep;
}

// ---------------------------------------------------------------------------
// Two launches total: the mega-kernel, then proj.
// ---------------------------------------------------------------------------
extern "C" void kernel_launch(void* const* d_in, const int* in_sizes, int n_in,
                              void* d_out, int out_size) {
    const float* x     = (const float*)d_in[0];
    const float* logit = (const float*)d_in[1];
    const float* gamma = (const float*)d_in[2];
    const float* beta  = (const float*)d_in[3];
    const float* wproj = (const float*)d_in[4];
    const float* bproj = (const float*)d_in[5];

    float* out        = (float*)d_out;
    float* out_sparse = out;
    float* out_feats  = out + (size_t)BB*CC*HW;
    float* out_coords = out_feats + BB*CELLS*256;
    float* out_keep   = out_coords + BB*CELLS*4;

    k_fused<<<BB*BLK_PER_B, 224>>>(x, (float4*)out_sparse, logit,
                                   out_keep, out_coords);
    k_proj<<<BB*CELLS, 256>>>(gamma, beta, wproj, bproj, out_feats);
}